// round 5
// baseline (speedup 1.0000x reference)
#include <cuda_runtime.h>
#include <cuda_bf16.h>
#include <math.h>
#include <stdint.h>

// Problem constants
#define PB 4096     // batch
#define PF 2048     // features
#define PK 64       // concepts
#define PD 8        // box dim
#define PN 1024     // K*2D
#define KD 512      // K*D

// GEMM tiling
#define BM 128
#define BN 128
#define BK 32
#define APAD 8
#define BPAD 8
#define NK (PF / BK)   // 64

// ---------------- scratch (__device__ globals) ----------------
__device__ __nv_bfloat16 g_Ahi[PB * PF];
__device__ __nv_bfloat16 g_Alo[PB * PF];
__device__ __nv_bfloat16 g_Whi[PF * PN];
__device__ __nv_bfloat16 g_Wlo[PF * PN];
__device__ float g_theta[PB * PN];    // GEMM output

// ---------------- PTX helpers ----------------
__device__ __forceinline__ void cpasync16(void* dst, const void* src) {
    uint32_t d = (uint32_t)__cvta_generic_to_shared(dst);
    asm volatile("cp.async.cg.shared.global [%0], [%1], 16;\n" :: "r"(d), "l"(src));
}
__device__ __forceinline__ void ldsm_x4(uint32_t* r, uint32_t addr) {
    asm volatile("ldmatrix.sync.aligned.m8n8.x4.shared.b16 {%0,%1,%2,%3}, [%4];\n"
                 : "=r"(r[0]), "=r"(r[1]), "=r"(r[2]), "=r"(r[3]) : "r"(addr));
}
__device__ __forceinline__ void ldsm_x2t(uint32_t* r, uint32_t addr) {
    asm volatile("ldmatrix.sync.aligned.m8n8.x2.trans.shared.b16 {%0,%1}, [%2];\n"
                 : "=r"(r[0]), "=r"(r[1]) : "r"(addr));
}
__device__ __forceinline__ void mma16816(float* c, const uint32_t* a, const uint32_t* b) {
    asm volatile(
        "mma.sync.aligned.m16n8k16.row.col.f32.bf16.bf16.f32 "
        "{%0,%1,%2,%3}, {%4,%5,%6,%7}, {%8,%9}, {%0,%1,%2,%3};\n"
        : "+f"(c[0]), "+f"(c[1]), "+f"(c[2]), "+f"(c[3])
        : "r"(a[0]), "r"(a[1]), "r"(a[2]), "r"(a[3]), "r"(b[0]), "r"(b[1]));
}
__device__ __forceinline__ float ex2_fast(float x) {
    float r; asm("ex2.approx.ftz.f32 %0, %1;" : "=f"(r) : "f"(x)); return r;
}
__device__ __forceinline__ float lg2_fast(float x) {
    float r; asm("lg2.approx.ftz.f32 %0, %1;" : "=f"(r) : "f"(x)); return r;
}

// ---------------- kernel: convert A (features) to bf16 hi/lo ----------------
__global__ void cvtA_kernel(const float* __restrict__ A) {
    int i = (blockIdx.x * 256 + threadIdx.x) * 4;
    float4 v = *(const float4*)(A + i);
    __nv_bfloat16 hx = __float2bfloat16(v.x);
    __nv_bfloat16 hy = __float2bfloat16(v.y);
    __nv_bfloat16 hz = __float2bfloat16(v.z);
    __nv_bfloat16 hw = __float2bfloat16(v.w);
    __nv_bfloat162 h01; h01.x = hx; h01.y = hy;
    __nv_bfloat162 h23; h23.x = hz; h23.y = hw;
    *(__nv_bfloat162*)(g_Ahi + i)     = h01;
    *(__nv_bfloat162*)(g_Ahi + i + 2) = h23;
    __nv_bfloat162 l01, l23;
    l01.x = __float2bfloat16(v.x - __bfloat162float(hx));
    l01.y = __float2bfloat16(v.y - __bfloat162float(hy));
    l23.x = __float2bfloat16(v.z - __bfloat162float(hz));
    l23.y = __float2bfloat16(v.w - __bfloat162float(hw));
    *(__nv_bfloat162*)(g_Alo + i)     = l01;
    *(__nv_bfloat162*)(g_Alo + i + 2) = l23;
}

// ---------------- kernel: transpose + split Wp (K,F,2D) -> W[f][n] hi/lo ----------------
__global__ void cvtW_kernel(const float* __restrict__ Wp) {
    int idx = blockIdx.x * 256 + threadIdx.x;   // idx = f*1024 + n
    if (idx < PF * PN) {
        int f = idx >> 10;
        int n = idx & 1023;
        float v = Wp[(n >> 4) * (PF * 16) + f * 16 + (n & 15)];
        __nv_bfloat16 h = __float2bfloat16(v);
        g_Whi[idx] = h;
        g_Wlo[idx] = __float2bfloat16(v - __bfloat162float(h));
    }
}

// ---------------- kernel: bf16x3 tensor-core GEMM ----------------
struct SmemT {
    __nv_bfloat16 Ahi[2][BM][BK + APAD];
    __nv_bfloat16 Alo[2][BM][BK + APAD];
    __nv_bfloat16 Bhi[2][BK][BN + BPAD];
    __nv_bfloat16 Blo[2][BK][BN + BPAD];
};

__global__ __launch_bounds__(256) void gemm3_kernel(const float* __restrict__ bias) {
    extern __shared__ char sm_raw[];
    SmemT* sm = (SmemT*)sm_raw;
    const int tid = threadIdx.x;
    const int warp = tid >> 5;
    const int l = tid & 31;
    const int wm = warp >> 2;       // 0..1
    const int wn = warp & 3;        // 0..3
    const int row0 = blockIdx.y * BM;
    const int col0 = blockIdx.x * BN;

    float acc[4][4][4];
#pragma unroll
    for (int mi = 0; mi < 4; mi++)
#pragma unroll
        for (int ni = 0; ni < 4; ni++)
#pragma unroll
            for (int r = 0; r < 4; r++) acc[mi][ni][r] = 0.f;

    const __nv_bfloat16* Ah = g_Ahi + (size_t)row0 * PF;
    const __nv_bfloat16* Al = g_Alo + (size_t)row0 * PF;
    const __nv_bfloat16* Bh = g_Whi + col0;
    const __nv_bfloat16* Bl = g_Wlo + col0;

    const int arow = tid >> 2;          // 0..63
    const int acol = (tid & 3) * 8;     // 0,8,16,24
    const int brow = tid >> 4;          // 0..15
    const int bcol = (tid & 15) * 8;    // 0..120

    auto load_stage = [&](int kt, int s) {
        int k0 = kt * BK;
        const __nv_bfloat16* ah = Ah + k0;
        const __nv_bfloat16* al = Al + k0;
#pragma unroll
        for (int r = 0; r < 2; r++) {
            int row = arow + r * 64;
            cpasync16(&sm->Ahi[s][row][acol], ah + (size_t)row * PF + acol);
            cpasync16(&sm->Alo[s][row][acol], al + (size_t)row * PF + acol);
        }
        const __nv_bfloat16* bh = Bh + (size_t)k0 * PN;
        const __nv_bfloat16* bl = Bl + (size_t)k0 * PN;
#pragma unroll
        for (int r = 0; r < 2; r++) {
            int row = brow + r * 16;
            cpasync16(&sm->Bhi[s][row][bcol], bh + (size_t)row * PN + bcol);
            cpasync16(&sm->Blo[s][row][bcol], bl + (size_t)row * PN + bcol);
        }
        asm volatile("cp.async.commit_group;\n");
    };

    load_stage(0, 0);

    const int lr16 = l & 15;
    const int lhalf = (l >> 4) * 8;

    for (int kt = 0; kt < NK; kt++) {
        const int s = kt & 1;
        if (kt + 1 < NK) {
            load_stage(kt + 1, s ^ 1);
            asm volatile("cp.async.wait_group 1;\n");
        } else {
            asm volatile("cp.async.wait_group 0;\n");
        }
        __syncthreads();

#pragma unroll
        for (int ks = 0; ks < 2; ks++) {
            const int kk = ks * 16;
            uint32_t ah4[4][4], al4[4][4], bh2[4][2], bl2[4][2];
#pragma unroll
            for (int mi = 0; mi < 4; mi++) {
                int mrow = wm * 64 + mi * 16 + lr16;
                uint32_t addr = (uint32_t)__cvta_generic_to_shared(&sm->Ahi[s][mrow][kk + lhalf]);
                ldsm_x4(ah4[mi], addr);
                addr = (uint32_t)__cvta_generic_to_shared(&sm->Alo[s][mrow][kk + lhalf]);
                ldsm_x4(al4[mi], addr);
            }
#pragma unroll
            for (int ni = 0; ni < 4; ni++) {
                int nc = wn * 32 + ni * 8;
                uint32_t addr = (uint32_t)__cvta_generic_to_shared(&sm->Bhi[s][kk + lr16][nc]);
                ldsm_x2t(bh2[ni], addr);
                addr = (uint32_t)__cvta_generic_to_shared(&sm->Blo[s][kk + lr16][nc]);
                ldsm_x2t(bl2[ni], addr);
            }
#pragma unroll
            for (int mi = 0; mi < 4; mi++)
#pragma unroll
                for (int ni = 0; ni < 4; ni++) {
                    mma16816(acc[mi][ni], ah4[mi], bh2[ni]);
                    mma16816(acc[mi][ni], ah4[mi], bl2[ni]);
                    mma16816(acc[mi][ni], al4[mi], bh2[ni]);
                }
        }
        __syncthreads();
    }

    // epilogue: add bias, store fp32 theta
    const int rbase = row0 + wm * 64 + (l >> 2);
    const int cbase = col0 + wn * 32 + (l & 3) * 2;
#pragma unroll
    for (int mi = 0; mi < 4; mi++) {
#pragma unroll
        for (int ni = 0; ni < 4; ni++) {
            int r = rbase + mi * 16;
            int c = cbase + ni * 8;
            float b0 = bias[c], b1 = bias[c + 1];
            float2 v0; v0.x = acc[mi][ni][0] + b0; v0.y = acc[mi][ni][1] + b1;
            *(float2*)(g_theta + (size_t)r * PN + c) = v0;
            float2 v1; v1.x = acc[mi][ni][2] + b0; v1.y = acc[mi][ni][3] + b1;
            *(float2*)(g_theta + (size_t)(r + 8) * PN + c) = v1;
        }
    }
}

// fast softplus: ln(1+e^x) with hardware MUFU
__device__ __forceinline__ float softplus_f(float x) {
    float e = __expf(-fabsf(x));
    return fmaxf(x, 0.f) + __logf(1.f + e);
}

// ---------------- fused kernel: per-b prep + pairwise cond + task logit ----------------
__global__ __launch_bounds__(256) void fused_kernel(const float* __restrict__ Wprob,
                                                    const float* __restrict__ bprob,
                                                    const float* __restrict__ Wbox,
                                                    const float* __restrict__ Wrel,
                                                    const float* __restrict__ bbox,
                                                    const float* __restrict__ brel,
                                                    float* __restrict__ out_task,
                                                    float* __restrict__ out_cp,
                                                    float* __restrict__ out_cond) {
    const int b = blockIdx.x;
    const int tid = threadIdx.x;

    __shared__ float s_ez[KD], s_eZ[KD], s_vinv[PK];
    __shared__ float s_cond[PK * PK];
    __shared__ float s_red[8];
    __shared__ float s_bd[2];

    // ---- prep phase: threads 0..63 handle k = tid ----
    if (tid < PK) {
        const int k = tid;
        const float* th = g_theta + (size_t)b * PN + k * 16;
        float4 t0 = *(const float4*)(th);
        float4 t1 = *(const float4*)(th + 4);
        float4 t2 = *(const float4*)(th + 8);
        float4 t3 = *(const float4*)(th + 12);
        float z[PD]  = {t0.x, t0.y, t0.z, t0.w, t1.x, t1.y, t1.z, t1.w};
        float w2[PD] = {t2.x, t2.y, t2.z, t2.w, t3.x, t3.y, t3.z, t3.w};

        float Z[PD], v[PD];
#pragma unroll
        for (int d = 0; d < PD; d++) {
            v[d] = softplus_f(w2[d]);    // Z - z >= 0
            Z[d] = z[d] + v[d];
        }

        // concept logit -> prob
        const float* wp = Wprob + k * 16;
        float logit = bprob[k];
#pragma unroll
        for (int d = 0; d < PD; d++) logit += z[d] * wp[d] + Z[d] * wp[8 + d];
        float p = 1.f / (1.f + __expf(-logit));
        out_cp[b * PK + k] = p;

        // box-dot partial: p * (z . Wbox[k][0:8] + Z . Wbox[k][8:16])
        const float* wb = Wbox + k * 16;
        float bd = 0.f;
#pragma unroll
        for (int d = 0; d < PD; d++) bd += z[d] * wb[d] + Z[d] * wb[8 + d];
        bd *= p;

        // exp tables (to smem) + scalar inverse box volume
        const float C10 = 14.426950408889634f;  // 10/ln2
        float vprod = 1.f;
#pragma unroll
        for (int d = 0; d < PD; d++) {
            s_ez[k * PD + d] = ex2_fast(z[d] * C10);
            s_eZ[k * PD + d] = ex2_fast(-Z[d] * C10);
            float sp2 = 2.f * v[d] + __logf(1.f + __expf(-2.f * v[d]));  // softplus(2v)
            vprod *= sp2;
        }
        s_vinv[k] = 1.f / vprod;

        // reduce bd within each of the 2 warps
        float s = bd;
#pragma unroll
        for (int off = 16; off; off >>= 1) s += __shfl_down_sync(0xffffffffu, s, off);
        if ((k & 31) == 0) s_bd[k >> 5] = s;
    }
    __syncthreads();

    // ---- pairwise phase: symmetric half-pairs ----
    const int i = tid & 63;
    const int g = tid >> 6;
    float ezi[PD], eZi[PD];
#pragma unroll
    for (int d = 0; d < PD; d += 4) {
        float4 a = *(const float4*)(s_ez + i * PD + d);
        ezi[d] = a.x; ezi[d+1] = a.y; ezi[d+2] = a.z; ezi[d+3] = a.w;
        float4 c = *(const float4*)(s_eZ + i * PD + d);
        eZi[d] = c.x; eZi[d+1] = c.y; eZi[d+2] = c.z; eZi[d+3] = c.w;
    }
    const float vinv_i = s_vinv[i];

    const float CLO = 1e-6f;
    const float CHI = 1.0f - 1e-6f;
    const float LN2P8 = 0.05328484f;   // ln(2)^8

    const int qmax = (g == 0) ? 9 : 8;
    for (int q = 0; q < qmax; q++) {
        const int off = g + 4 * q;
        const int j = (i + off) & 63;
        float prod = LN2P8;
#pragma unroll
        for (int d = 0; d < PD; d++) {
            float S = ezi[d] + s_ez[j * PD + d];
            float T = eZi[d] + s_eZ[j * PD + d];
            float m = lg2_fast(S * T);
            float e = ex2_fast(-0.2f * m);     // (S*T)^{-1/5} = exp(2u)
            prod *= lg2_fast(1.f + e);         // log2-domain softplus(2u)
        }
        float ci = fminf(fmaxf(prod * s_vinv[j], CLO), CHI);  // cond(i,j)
        float cj = fminf(fmaxf(prod * vinv_i,   CLO), CHI);   // cond(j,i)
        s_cond[i * PK + j] = ci;
        s_cond[j * PK + i] = cj;
    }
    __syncthreads();

    // coalesced writeout + fused Wrel dot
    float relsum = 0.f;
    float* outp = out_cond + (size_t)b * (PK * PK);
#pragma unroll
    for (int r = 0; r < 4; r++) {
        int idx = (tid + r * 256) * 4;
        float4 c = *(const float4*)(s_cond + idx);
        float4 w = *(const float4*)(Wrel + idx);
        relsum += c.x * w.x + c.y * w.y + c.z * w.z + c.w * w.w;
        *(float4*)(outp + idx) = c;
    }

#pragma unroll
    for (int off = 16; off; off >>= 1) relsum += __shfl_down_sync(0xffffffffu, relsum, off);
    if ((tid & 31) == 0) s_red[tid >> 5] = relsum;
    __syncthreads();
    if (tid == 0) {
        float tot = 0.f;
#pragma unroll
        for (int w = 0; w < 8; w++) tot += s_red[w];
        tot += s_bd[0] + s_bd[1] + bbox[0] + brel[0];
        out_task[b] = 1.f / (1.f + __expf(-tot));
    }
}

// ---------------- launch ----------------
extern "C" void kernel_launch(void* const* d_in, const int* in_sizes, int n_in,
                              void* d_out, int out_size) {
    const float* features = (const float*)d_in[0];  // (B,F)
    const float* Wp       = (const float*)d_in[1];  // (K,F,2D)
    const float* bp       = (const float*)d_in[2];  // (K,2D)
    const float* Wprob    = (const float*)d_in[3];  // (K,2D)
    const float* bprob    = (const float*)d_in[4];  // (K,)
    const float* Wbox     = (const float*)d_in[5];  // (K*2D,1)
    const float* bbox     = (const float*)d_in[6];  // (1,)
    const float* Wrel     = (const float*)d_in[7];  // (K*K,1)
    const float* brel     = (const float*)d_in[8];  // (1,)

    float* out = (float*)d_out;
    float* out_task = out;                      // [B]
    float* out_cp   = out + PB;                 // [B,K]
    float* out_cond = out + PB + PB * PK;       // [B,K,K]

    // 0. conversions
    cvtA_kernel<<<PB * PF / (256 * 4), 256>>>(features);
    cvtW_kernel<<<(PF * PN + 255) / 256, 256>>>(Wp);

    // 1. bf16x3 tensor-core GEMM
    int smem_bytes = (int)sizeof(SmemT);
    cudaFuncSetAttribute(gemm3_kernel, cudaFuncAttributeMaxDynamicSharedMemorySize, smem_bytes);
    dim3 ggrid(PN / BN, PB / BM);   // (8, 32)
    gemm3_kernel<<<ggrid, 256, smem_bytes>>>(bp);

    // 2. fused prep + pairwise + task logit
    fused_kernel<<<PB, 256>>>(Wprob, bprob, Wbox, Wrel, bbox, brel,
                              out_task, out_cp, out_cond);
}

// round 6
// speedup vs baseline: 1.0700x; 1.0700x over previous
#include <cuda_runtime.h>
#include <cuda_bf16.h>
#include <math.h>
#include <stdint.h>

// Problem constants
#define PB 4096     // batch
#define PF 2048     // features
#define PK 64       // concepts
#define PD 8        // box dim
#define PN 1024     // K*2D
#define KD 512      // K*D

// GEMM tiling
#define BM 128
#define BN 128
#define BK 32
#define APAD 8
#define BPAD 8
#define NK (PF / BK)   // 64

// ---------------- scratch (__device__ globals) ----------------
__device__ __nv_bfloat16 g_Ahi[PB * PF];
__device__ __nv_bfloat16 g_Alo[PB * PF];
__device__ __nv_bfloat16 g_Whi[PF * PN];
__device__ __nv_bfloat16 g_Wlo[PF * PN];
__device__ float g_theta[PB * PN];    // GEMM output

// ---------------- PTX helpers ----------------
__device__ __forceinline__ void cpasync16(void* dst, const void* src) {
    uint32_t d = (uint32_t)__cvta_generic_to_shared(dst);
    asm volatile("cp.async.cg.shared.global [%0], [%1], 16;\n" :: "r"(d), "l"(src));
}
__device__ __forceinline__ void ldsm_x4(uint32_t* r, uint32_t addr) {
    asm volatile("ldmatrix.sync.aligned.m8n8.x4.shared.b16 {%0,%1,%2,%3}, [%4];\n"
                 : "=r"(r[0]), "=r"(r[1]), "=r"(r[2]), "=r"(r[3]) : "r"(addr));
}
__device__ __forceinline__ void ldsm_x2t(uint32_t* r, uint32_t addr) {
    asm volatile("ldmatrix.sync.aligned.m8n8.x2.trans.shared.b16 {%0,%1}, [%2];\n"
                 : "=r"(r[0]), "=r"(r[1]) : "r"(addr));
}
__device__ __forceinline__ void mma16816(float* c, const uint32_t* a, const uint32_t* b) {
    asm volatile(
        "mma.sync.aligned.m16n8k16.row.col.f32.bf16.bf16.f32 "
        "{%0,%1,%2,%3}, {%4,%5,%6,%7}, {%8,%9}, {%0,%1,%2,%3};\n"
        : "+f"(c[0]), "+f"(c[1]), "+f"(c[2]), "+f"(c[3])
        : "r"(a[0]), "r"(a[1]), "r"(a[2]), "r"(a[3]), "r"(b[0]), "r"(b[1]));
}
__device__ __forceinline__ float ex2_fast(float x) {
    float r; asm("ex2.approx.ftz.f32 %0, %1;" : "=f"(r) : "f"(x)); return r;
}
__device__ __forceinline__ float lg2_fast(float x) {
    float r; asm("lg2.approx.ftz.f32 %0, %1;" : "=f"(r) : "f"(x)); return r;
}

// ---------------- kernel: convert A (features) to bf16 hi/lo ----------------
__global__ void cvtA_kernel(const float* __restrict__ A) {
    int i = (blockIdx.x * 256 + threadIdx.x) * 4;
    float4 v = *(const float4*)(A + i);
    __nv_bfloat16 hx = __float2bfloat16(v.x);
    __nv_bfloat16 hy = __float2bfloat16(v.y);
    __nv_bfloat16 hz = __float2bfloat16(v.z);
    __nv_bfloat16 hw = __float2bfloat16(v.w);
    __nv_bfloat162 h01; h01.x = hx; h01.y = hy;
    __nv_bfloat162 h23; h23.x = hz; h23.y = hw;
    *(__nv_bfloat162*)(g_Ahi + i)     = h01;
    *(__nv_bfloat162*)(g_Ahi + i + 2) = h23;
    __nv_bfloat162 l01, l23;
    l01.x = __float2bfloat16(v.x - __bfloat162float(hx));
    l01.y = __float2bfloat16(v.y - __bfloat162float(hy));
    l23.x = __float2bfloat16(v.z - __bfloat162float(hz));
    l23.y = __float2bfloat16(v.w - __bfloat162float(hw));
    *(__nv_bfloat162*)(g_Alo + i)     = l01;
    *(__nv_bfloat162*)(g_Alo + i + 2) = l23;
}

// ---------------- kernel: transpose + split Wp (K,F,2D) -> W[f][n] hi/lo ----------------
__global__ void cvtW_kernel(const float* __restrict__ Wp) {
    int idx = blockIdx.x * 256 + threadIdx.x;   // idx = f*1024 + n
    if (idx < PF * PN) {
        int f = idx >> 10;
        int n = idx & 1023;
        float v = Wp[(n >> 4) * (PF * 16) + f * 16 + (n & 15)];
        __nv_bfloat16 h = __float2bfloat16(v);
        g_Whi[idx] = h;
        g_Wlo[idx] = __float2bfloat16(v - __bfloat162float(h));
    }
}

// ---------------- kernel: bf16x3 tensor-core GEMM ----------------
struct SmemT {
    __nv_bfloat16 Ahi[2][BM][BK + APAD];
    __nv_bfloat16 Alo[2][BM][BK + APAD];
    __nv_bfloat16 Bhi[2][BK][BN + BPAD];
    __nv_bfloat16 Blo[2][BK][BN + BPAD];
};

__global__ __launch_bounds__(256, 2) void gemm3_kernel(const float* __restrict__ bias) {
    extern __shared__ char sm_raw[];
    SmemT* sm = (SmemT*)sm_raw;
    const int tid = threadIdx.x;
    const int warp = tid >> 5;
    const int l = tid & 31;
    const int wm = warp >> 2;       // 0..1
    const int wn = warp & 3;        // 0..3
    const int row0 = blockIdx.y * BM;
    const int col0 = blockIdx.x * BN;

    float acc[4][4][4];
#pragma unroll
    for (int mi = 0; mi < 4; mi++)
#pragma unroll
        for (int ni = 0; ni < 4; ni++)
#pragma unroll
            for (int r = 0; r < 4; r++) acc[mi][ni][r] = 0.f;

    const __nv_bfloat16* Ah = g_Ahi + (size_t)row0 * PF;
    const __nv_bfloat16* Al = g_Alo + (size_t)row0 * PF;
    const __nv_bfloat16* Bh = g_Whi + col0;
    const __nv_bfloat16* Bl = g_Wlo + col0;

    const int arow = tid >> 2;          // 0..63
    const int acol = (tid & 3) * 8;     // 0,8,16,24
    const int brow = tid >> 4;          // 0..15
    const int bcol = (tid & 15) * 8;    // 0..120

    auto load_stage = [&](int kt, int s) {
        int k0 = kt * BK;
        const __nv_bfloat16* ah = Ah + k0;
        const __nv_bfloat16* al = Al + k0;
#pragma unroll
        for (int r = 0; r < 2; r++) {
            int row = arow + r * 64;
            cpasync16(&sm->Ahi[s][row][acol], ah + (size_t)row * PF + acol);
            cpasync16(&sm->Alo[s][row][acol], al + (size_t)row * PF + acol);
        }
        const __nv_bfloat16* bh = Bh + (size_t)k0 * PN;
        const __nv_bfloat16* bl = Bl + (size_t)k0 * PN;
#pragma unroll
        for (int r = 0; r < 2; r++) {
            int row = brow + r * 16;
            cpasync16(&sm->Bhi[s][row][bcol], bh + (size_t)row * PN + bcol);
            cpasync16(&sm->Blo[s][row][bcol], bl + (size_t)row * PN + bcol);
        }
        asm volatile("cp.async.commit_group;\n");
    };

    load_stage(0, 0);

    const int lr16 = l & 15;
    const int lhalf = (l >> 4) * 8;

    for (int kt = 0; kt < NK; kt++) {
        const int s = kt & 1;
        if (kt + 1 < NK) {
            load_stage(kt + 1, s ^ 1);
            asm volatile("cp.async.wait_group 1;\n");
        } else {
            asm volatile("cp.async.wait_group 0;\n");
        }
        __syncthreads();

#pragma unroll
        for (int ks = 0; ks < 2; ks++) {
            const int kk = ks * 16;
            uint32_t a4[4][4], bh2[4][2], bl2[4][2];
            // B fragments (held across both product batches)
#pragma unroll
            for (int ni = 0; ni < 4; ni++) {
                int nc = wn * 32 + ni * 8;
                uint32_t addr = (uint32_t)__cvta_generic_to_shared(&sm->Bhi[s][kk + lr16][nc]);
                ldsm_x2t(bh2[ni], addr);
                addr = (uint32_t)__cvta_generic_to_shared(&sm->Blo[s][kk + lr16][nc]);
                ldsm_x2t(bl2[ni], addr);
            }
            // batch 1: Ahi * {Bhi, Blo}
#pragma unroll
            for (int mi = 0; mi < 4; mi++) {
                int mrow = wm * 64 + mi * 16 + lr16;
                uint32_t addr = (uint32_t)__cvta_generic_to_shared(&sm->Ahi[s][mrow][kk + lhalf]);
                ldsm_x4(a4[mi], addr);
            }
#pragma unroll
            for (int mi = 0; mi < 4; mi++)
#pragma unroll
                for (int ni = 0; ni < 4; ni++) {
                    mma16816(acc[mi][ni], a4[mi], bh2[ni]);
                    mma16816(acc[mi][ni], a4[mi], bl2[ni]);
                }
            // batch 2: Alo * Bhi (reuse a4 registers)
#pragma unroll
            for (int mi = 0; mi < 4; mi++) {
                int mrow = wm * 64 + mi * 16 + lr16;
                uint32_t addr = (uint32_t)__cvta_generic_to_shared(&sm->Alo[s][mrow][kk + lhalf]);
                ldsm_x4(a4[mi], addr);
            }
#pragma unroll
            for (int mi = 0; mi < 4; mi++)
#pragma unroll
                for (int ni = 0; ni < 4; ni++)
                    mma16816(acc[mi][ni], a4[mi], bh2[ni]);
        }
        __syncthreads();
    }

    // epilogue: add bias, store fp32 theta
    const int rbase = row0 + wm * 64 + (l >> 2);
    const int cbase = col0 + wn * 32 + (l & 3) * 2;
#pragma unroll
    for (int mi = 0; mi < 4; mi++) {
#pragma unroll
        for (int ni = 0; ni < 4; ni++) {
            int r = rbase + mi * 16;
            int c = cbase + ni * 8;
            float b0 = bias[c], b1 = bias[c + 1];
            float2 v0; v0.x = acc[mi][ni][0] + b0; v0.y = acc[mi][ni][1] + b1;
            *(float2*)(g_theta + (size_t)r * PN + c) = v0;
            float2 v1; v1.x = acc[mi][ni][2] + b0; v1.y = acc[mi][ni][3] + b1;
            *(float2*)(g_theta + (size_t)(r + 8) * PN + c) = v1;
        }
    }
}

// fast softplus: ln(1+e^x) with hardware MUFU
__device__ __forceinline__ float softplus_f(float x) {
    float e = __expf(-fabsf(x));
    return fmaxf(x, 0.f) + __logf(1.f + e);
}

// ---------------- fused kernel: per-b prep + pairwise cond + task logit ----------------
// Transposed smem tables: s_ez[d*64+k] (bank-conflict-free for strided j access)
__global__ __launch_bounds__(256) void fused_kernel(const float* __restrict__ Wprob,
                                                    const float* __restrict__ bprob,
                                                    const float* __restrict__ Wbox,
                                                    const float* __restrict__ Wrel,
                                                    const float* __restrict__ bbox,
                                                    const float* __restrict__ brel,
                                                    float* __restrict__ out_task,
                                                    float* __restrict__ out_cp,
                                                    float* __restrict__ out_cond) {
    const int b = blockIdx.x;
    const int tid = threadIdx.x;

    __shared__ float s_ez[KD], s_eZ[KD], s_vinv[PK];   // [d][k] layout
    __shared__ float s_cond[PK * PK];
    __shared__ float s_red[8];
    __shared__ float s_bd[2];

    // ---- prep phase: threads 0..63 handle k = tid ----
    if (tid < PK) {
        const int k = tid;
        const float* th = g_theta + (size_t)b * PN + k * 16;
        float4 t0 = *(const float4*)(th);
        float4 t1 = *(const float4*)(th + 4);
        float4 t2 = *(const float4*)(th + 8);
        float4 t3 = *(const float4*)(th + 12);
        float z[PD]  = {t0.x, t0.y, t0.z, t0.w, t1.x, t1.y, t1.z, t1.w};
        float w2[PD] = {t2.x, t2.y, t2.z, t2.w, t3.x, t3.y, t3.z, t3.w};

        float Z[PD], v[PD];
#pragma unroll
        for (int d = 0; d < PD; d++) {
            v[d] = softplus_f(w2[d]);    // Z - z >= 0
            Z[d] = z[d] + v[d];
        }

        // concept logit -> prob
        const float* wp = Wprob + k * 16;
        float logit = bprob[k];
#pragma unroll
        for (int d = 0; d < PD; d++) logit += z[d] * wp[d] + Z[d] * wp[8 + d];
        float p = 1.f / (1.f + __expf(-logit));
        out_cp[b * PK + k] = p;

        // box-dot partial: p * (z . Wbox[k][0:8] + Z . Wbox[k][8:16])
        const float* wb = Wbox + k * 16;
        float bd = 0.f;
#pragma unroll
        for (int d = 0; d < PD; d++) bd += z[d] * wb[d] + Z[d] * wb[8 + d];
        bd *= p;

        // exp tables (transposed smem) + scalar inverse box volume
        const float C10 = 14.426950408889634f;  // 10/ln2
        float vprod = 1.f;
#pragma unroll
        for (int d = 0; d < PD; d++) {
            s_ez[d * PK + k] = ex2_fast(z[d] * C10);
            s_eZ[d * PK + k] = ex2_fast(-Z[d] * C10);
            float sp2 = 2.f * v[d] + __logf(1.f + __expf(-2.f * v[d]));  // softplus(2v)
            vprod *= sp2;
        }
        s_vinv[k] = 1.f / vprod;

        // reduce bd within each of the 2 warps
        float s = bd;
#pragma unroll
        for (int off = 16; off; off >>= 1) s += __shfl_down_sync(0xffffffffu, s, off);
        if ((k & 31) == 0) s_bd[k >> 5] = s;
    }
    __syncthreads();

    // ---- pairwise phase: symmetric half-pairs ----
    const int i = tid & 63;
    const int g = tid >> 6;
    float ezi[PD], eZi[PD];
#pragma unroll
    for (int d = 0; d < PD; d++) {
        ezi[d] = s_ez[d * PK + i];
        eZi[d] = s_eZ[d * PK + i];
    }
    const float vinv_i = s_vinv[i];

    const float CLO = 1e-6f;
    const float CHI = 1.0f - 1e-6f;
    const float LN2P8 = 0.05328484f;   // ln(2)^8

    const int qmax = (g == 0) ? 9 : 8;
    for (int q = 0; q < qmax; q++) {
        const int off = g + 4 * q;
        const int j = (i + off) & 63;
        float prod = LN2P8;
#pragma unroll
        for (int d = 0; d < PD; d++) {
            float S = ezi[d] + s_ez[d * PK + j];
            float T = eZi[d] + s_eZ[d * PK + j];
            float m = lg2_fast(S * T);
            float e = ex2_fast(-0.2f * m);     // (S*T)^{-1/5} = exp(2u)
            prod *= lg2_fast(1.f + e);         // log2-domain softplus(2u)
        }
        float ci = fminf(fmaxf(prod * s_vinv[j], CLO), CHI);  // cond(i,j)
        float cj = fminf(fmaxf(prod * vinv_i,   CLO), CHI);   // cond(j,i)
        s_cond[i * PK + j] = ci;
        s_cond[j * PK + i] = cj;
    }
    __syncthreads();

    // coalesced writeout + fused Wrel dot
    float relsum = 0.f;
    float* outp = out_cond + (size_t)b * (PK * PK);
#pragma unroll
    for (int r = 0; r < 4; r++) {
        int idx = (tid + r * 256) * 4;
        float4 c = *(const float4*)(s_cond + idx);
        float4 w = *(const float4*)(Wrel + idx);
        relsum += c.x * w.x + c.y * w.y + c.z * w.z + c.w * w.w;
        *(float4*)(outp + idx) = c;
    }

#pragma unroll
    for (int off = 16; off; off >>= 1) relsum += __shfl_down_sync(0xffffffffu, relsum, off);
    if ((tid & 31) == 0) s_red[tid >> 5] = relsum;
    __syncthreads();
    if (tid == 0) {
        float tot = 0.f;
#pragma unroll
        for (int w = 0; w < 8; w++) tot += s_red[w];
        tot += s_bd[0] + s_bd[1] + bbox[0] + brel[0];
        out_task[b] = 1.f / (1.f + __expf(-tot));
    }
}

// ---------------- launch ----------------
extern "C" void kernel_launch(void* const* d_in, const int* in_sizes, int n_in,
                              void* d_out, int out_size) {
    const float* features = (const float*)d_in[0];  // (B,F)
    const float* Wp       = (const float*)d_in[1];  // (K,F,2D)
    const float* bp       = (const float*)d_in[2];  // (K,2D)
    const float* Wprob    = (const float*)d_in[3];  // (K,2D)
    const float* bprob    = (const float*)d_in[4];  // (K,)
    const float* Wbox     = (const float*)d_in[5];  // (K*2D,1)
    const float* bbox     = (const float*)d_in[6];  // (1,)
    const float* Wrel     = (const float*)d_in[7];  // (K*K,1)
    const float* brel     = (const float*)d_in[8];  // (1,)

    float* out = (float*)d_out;
    float* out_task = out;                      // [B]
    float* out_cp   = out + PB;                 // [B,K]
    float* out_cond = out + PB + PB * PK;       // [B,K,K]

    // 0. conversions
    cvtA_kernel<<<PB * PF / (256 * 4), 256>>>(features);
    cvtW_kernel<<<(PF * PN + 255) / 256, 256>>>(Wp);

    // 1. bf16x3 tensor-core GEMM (2 CTAs/SM -> single wave over 256 CTAs)
    int smem_bytes = (int)sizeof(SmemT);
    cudaFuncSetAttribute(gemm3_kernel, cudaFuncAttributeMaxDynamicSharedMemorySize, smem_bytes);
    dim3 ggrid(PN / BN, PB / BM);   // (8, 32)
    gemm3_kernel<<<ggrid, 256, smem_bytes>>>(bp);

    // 2. fused prep + pairwise + task logit
    fused_kernel<<<PB, 256>>>(Wprob, bprob, Wbox, Wrel, bbox, brel,
                              out_task, out_cp, out_cond);
}